// round 7
// baseline (speedup 1.0000x reference)
#include <cuda_runtime.h>
#include <cuda_bf16.h>
#include <cstdint>

// dense_image_warp: out[b,y,x,c] = bilinear(image, (y,x) - flow[b,y,x])
// B=8, H=256, W=256, C=64 (fp32).
// One thread per float4 (4 channels) at one (y,x), over all 8 batches
// (4 iterations x 2 pixels). Corner gathers via cp.async.cg (16B) into a
// 2-stage smem ping-pong: truly asynchronous, bypasses L1, cannot be
// re-serialized by ptxas. No block-level syncs (per-thread cp.async groups).

__device__ __forceinline__ void stcs4(float4* p, float4 v) {
    asm volatile("st.global.cs.v4.f32 [%0], {%1,%2,%3,%4};"
                 :: "l"(p), "f"(v.x), "f"(v.y), "f"(v.z), "f"(v.w) : "memory");
}

__device__ __forceinline__ void cpasync16(uint32_t dst, const void* src) {
    asm volatile("cp.async.cg.shared.global [%0], [%1], 16;"
                 :: "r"(dst), "l"(src));
}

__device__ __forceinline__ uint32_t smem_u32(const void* p) {
    uint32_t a;
    asm("{ .reg .u64 t; cvta.to.shared.u64 t, %1; cvt.u32.u64 %0, t; }"
        : "=r"(a) : "l"(p));
    return a;
}

__device__ __forceinline__ float4 lerp2d(float4 tl, float4 tr, float4 bl, float4 br,
                                         float ax, float ay) {
    float4 r;
    float top, bot;
    top = fmaf(ax, tr.x - tl.x, tl.x);
    bot = fmaf(ax, br.x - bl.x, bl.x);
    r.x = fmaf(ay, bot - top, top);
    top = fmaf(ax, tr.y - tl.y, tl.y);
    bot = fmaf(ax, br.y - bl.y, bl.y);
    r.y = fmaf(ay, bot - top, top);
    top = fmaf(ax, tr.z - tl.z, tl.z);
    bot = fmaf(ax, br.z - bl.z, bl.z);
    r.z = fmaf(ay, bot - top, top);
    top = fmaf(ax, tr.w - tl.w, tl.w);
    bot = fmaf(ax, br.w - bl.w, bl.w);
    r.w = fmaf(ay, bot - top, top);
    return r;
}

// Image base (float4 units) + weights for query (y,x)-f in batch b.
__device__ __forceinline__ int mkbase(int b, int y, int x, int c4, float2 f,
                                      float& ax, float& ay) {
    const float qy = (float)y - f.x;
    const float qx = (float)x - f.y;
    const float fy = fminf(fmaxf(floorf(qy), 0.0f), 254.0f);
    const float fx = fminf(fmaxf(floorf(qx), 0.0f), 254.0f);
    ay = fminf(fmaxf(qy - fy, 0.0f), 1.0f);
    ax = fminf(fmaxf(qx - fx, 0.0f), 1.0f);
    return ((((b << 8) + (int)fy) << 8) + (int)fx) * 16 + c4;
}

// Issue 8 corner cp.asyncs for iteration j (batches j and j+4) into stage j&1.
// sbase = smem addr of this thread's stage-0 corner-0 slot.
__device__ __forceinline__ void issue_stage(const float4* __restrict__ img,
                                            uint32_t sbase, int j,
                                            int y, int x, int c4,
                                            float2 fa, float2 fb,
                                            float* ax0, float* ay0,
                                            float* ax1, float* ay1) {
    const int s = j & 1;
    const int b0 = mkbase(j,     y, x, c4, fa, ax0[s], ay0[s]);
    const int b1 = mkbase(j + 4, y, x, c4, fb, ax1[s], ay1[s]);
    const uint32_t d = sbase + s * 16384;          // stage stride: 8*128*16
    cpasync16(d + 0 * 2048, img + b0);
    cpasync16(d + 1 * 2048, img + b0 + 16);
    cpasync16(d + 2 * 2048, img + b0 + 16 * 256);
    cpasync16(d + 3 * 2048, img + b0 + 16 * 256 + 16);
    cpasync16(d + 4 * 2048, img + b1);
    cpasync16(d + 5 * 2048, img + b1 + 16);
    cpasync16(d + 6 * 2048, img + b1 + 16 * 256);
    cpasync16(d + 7 * 2048, img + b1 + 16 * 256 + 16);
    asm volatile("cp.async.commit_group;" ::: "memory");
}

__global__ __launch_bounds__(128) void warp_kernel(
    const float4* __restrict__ img,    // [B,H,W,C] as float4, pixel stride 16
    const float2* __restrict__ flow,   // [B,H,W,2] as float2, one per pixel
    float4* __restrict__ out)
{
    // buf[stage][corner][thread]: thread-stride 16B -> conflict-free LDS.128
    __shared__ float4 buf[2][8][128];

    const int t   = threadIdx.x;
    const int tid = blockIdx.x * 128 + t;   // 0..2^20-1
    const int c4  = tid & 15;               // channel group 0..15
    const int p   = tid >> 4;               // (y,x) pixel 0..65535
    const int x   = p & 255;
    const int y   = p >> 8;

    const uint32_t sbase = smem_u32(&buf[0][0][t]);

    float ax0[2], ay0[2], ax1[2], ay1[2];

    // Prologue: issue stages for iterations 0 and 1; prefetch flow for it 2.
    float2 f0 = __ldg(&flow[p]);
    float2 f1 = __ldg(&flow[p + 4 * 65536]);
    issue_stage(img, sbase, 0, y, x, c4, f0, f1, ax0, ay0, ax1, ay1);
    f0 = __ldg(&flow[p + 1 * 65536]);
    f1 = __ldg(&flow[p + 5 * 65536]);
    issue_stage(img, sbase, 1, y, x, c4, f0, f1, ax0, ay0, ax1, ay1);
    f0 = __ldg(&flow[p + 2 * 65536]);
    f1 = __ldg(&flow[p + 6 * 65536]);

    #pragma unroll
    for (int it = 0; it < 4; ++it) {
        // Wait for stage 'it' (leave the newer group in flight).
        if (it < 3) asm volatile("cp.async.wait_group 1;" ::: "memory");
        else        asm volatile("cp.async.wait_group 0;" ::: "memory");

        const int s = it & 1;
        const float4 tl0 = buf[s][0][t];
        const float4 tr0 = buf[s][1][t];
        const float4 bl0 = buf[s][2][t];
        const float4 br0 = buf[s][3][t];
        const float4 tl1 = buf[s][4][t];
        const float4 tr1 = buf[s][5][t];
        const float4 bl1 = buf[s][6][t];
        const float4 br1 = buf[s][7][t];

        const float cax0 = ax0[s], cay0 = ay0[s];
        const float cax1 = ax1[s], cay1 = ay1[s];

        // Refill this stage slot with iteration it+2 before the heavy math.
        if (it + 2 < 4) {
            issue_stage(img, sbase, it + 2, y, x, c4, f0, f1, ax0, ay0, ax1, ay1);
            if (it + 3 < 4) {
                f0 = __ldg(&flow[p + (it + 3) * 65536]);
                f1 = __ldg(&flow[p + (it + 7) * 65536]);
            }
        }

        const float4 r0 = lerp2d(tl0, tr0, bl0, br0, cax0, cay0);
        const float4 r1 = lerp2d(tl1, tr1, bl1, br1, cax1, cay1);

        stcs4(out + tid + it * 1048576, r0);
        stcs4(out + tid + (it + 4) * 1048576, r1);
    }
}

extern "C" void kernel_launch(void* const* d_in, const int* in_sizes, int n_in,
                              void* d_out, int out_size)
{
    const float4* img  = (const float4*)d_in[0];
    const float2* flow = (const float2*)d_in[1];
    float4* out = (float4*)d_out;

    // 65536 (y,x) pixels * 16 channel-groups = 1048576 threads, 8 pixels each
    const int threads = 1 << 20;
    const int block = 128;
    const int grid = threads / block;  // 8192
    warp_kernel<<<grid, block>>>(img, flow, out);
}

// round 9
// speedup vs baseline: 1.0832x; 1.0832x over previous
#include <cuda_runtime.h>
#include <cuda_bf16.h>

// dense_image_warp: out[b,y,x,c] = bilinear(image, (y,x) - flow[b,y,x])
// B=8, H=256, W=256, C=64 (fp32).
// One thread per float4 (4 channels) at one (y,x), looping over all 8 batches
// (4 iterations x 2 pixels), flow prefetched one iteration ahead (R5 winner).
// __launch_bounds__(256, 8) forces 32 regs -> 64-warp occupancy to maximize
// chip-wide outstanding DRAM misses (kernel is latency-bound, not pipe-bound).

__device__ __forceinline__ void stcs4(float4* p, float4 v) {
    asm volatile("st.global.cs.v4.f32 [%0], {%1,%2,%3,%4};"
                 :: "l"(p), "f"(v.x), "f"(v.y), "f"(v.z), "f"(v.w) : "memory");
}

__device__ __forceinline__ float4 lerp2d(float4 tl, float4 tr, float4 bl, float4 br,
                                         float ax, float ay) {
    float4 r;
    float top, bot;
    top = fmaf(ax, tr.x - tl.x, tl.x);
    bot = fmaf(ax, br.x - bl.x, bl.x);
    r.x = fmaf(ay, bot - top, top);
    top = fmaf(ax, tr.y - tl.y, tl.y);
    bot = fmaf(ax, br.y - bl.y, bl.y);
    r.y = fmaf(ay, bot - top, top);
    top = fmaf(ax, tr.z - tl.z, tl.z);
    bot = fmaf(ax, br.z - bl.z, bl.z);
    r.z = fmaf(ay, bot - top, top);
    top = fmaf(ax, tr.w - tl.w, tl.w);
    bot = fmaf(ax, br.w - bl.w, bl.w);
    r.w = fmaf(ay, bot - top, top);
    return r;
}

// Image base (float4 units) + weights for query (y,x)-f in batch b.
__device__ __forceinline__ int mkbase(int b, int y, int x, int c4, float2 f,
                                      float& ax, float& ay) {
    const float qy = (float)y - f.x;
    const float qx = (float)x - f.y;
    const float fy = fminf(fmaxf(floorf(qy), 0.0f), 254.0f);
    const float fx = fminf(fmaxf(floorf(qx), 0.0f), 254.0f);
    ay = fminf(fmaxf(qy - fy, 0.0f), 1.0f);
    ax = fminf(fmaxf(qx - fx, 0.0f), 1.0f);
    return ((((b << 8) + (int)fy) << 8) + (int)fx) * 16 + c4;
}

__global__ __launch_bounds__(256, 8) void warp_kernel(
    const float4* __restrict__ img,    // [B,H,W,C] as float4, pixel stride 16
    const float2* __restrict__ flow,   // [B,H,W,2] as float2, one per pixel
    float4* __restrict__ out)
{
    const int tid = blockIdx.x * blockDim.x + threadIdx.x;  // 0..2^20-1
    const int c4 = tid & 15;          // channel group 0..15
    const int p  = tid >> 4;          // (y,x) pixel index 0..65535
    const int x  = p & 255;
    const int y  = p >> 8;

    // Prologue: flow for batches 0 and 4
    float2 f0 = __ldg(&flow[p]);
    float2 f1 = __ldg(&flow[p + 4 * 65536]);

    #pragma unroll
    for (int it = 0; it < 4; ++it) {
        // This iteration handles batches it and it+4.
        float ax0, ay0, ax1, ay1;
        const int base0 = mkbase(it,     y, x, c4, f0, ax0, ay0);
        const int base1 = mkbase(it + 4, y, x, c4, f1, ax1, ay1);

        // 8 independent fully-coalesced 128-bit gathers
        const float4 tl0 = __ldg(img + base0);
        const float4 tr0 = __ldg(img + base0 + 16);
        const float4 bl0 = __ldg(img + base0 + 16 * 256);
        const float4 br0 = __ldg(img + base0 + 16 * 256 + 16);
        const float4 tl1 = __ldg(img + base1);
        const float4 tr1 = __ldg(img + base1 + 16);
        const float4 bl1 = __ldg(img + base1 + 16 * 256);
        const float4 br1 = __ldg(img + base1 + 16 * 256 + 16);

        // Prefetch next iteration's flow while gathers are in flight
        if (it < 3) {
            f0 = __ldg(&flow[p + (it + 1) * 65536]);
            f1 = __ldg(&flow[p + (it + 5) * 65536]);
        }

        const float4 r0 = lerp2d(tl0, tr0, bl0, br0, ax0, ay0);
        const float4 r1 = lerp2d(tl1, tr1, bl1, br1, ax1, ay1);

        // out offset (float4): (b*65536 + p)*16 + c4 = tid + b*1048576
        stcs4(out + tid + it * 1048576, r0);
        stcs4(out + tid + (it + 4) * 1048576, r1);
    }
}

extern "C" void kernel_launch(void* const* d_in, const int* in_sizes, int n_in,
                              void* d_out, int out_size)
{
    const float4* img  = (const float4*)d_in[0];
    const float2* flow = (const float2*)d_in[1];
    float4* out = (float4*)d_out;

    // 65536 (y,x) pixels * 16 channel-groups = 1048576 threads, 8 pixels each
    const int threads = 1 << 20;
    const int block = 256;
    const int grid = threads / block;  // 4096
    warp_kernel<<<grid, block>>>(img, flow, out);
}